// round 1
// baseline (speedup 1.0000x reference)
#include <cuda_runtime.h>
#include <cuda_fp16.h>
#include <cstdint>

// ---------------------------------------------------------------------------
// StyledLayer: upsample2x(bilinear, half-pixel) -> style-modulate ->
// conv3x3 (shared weights) -> demodulate -> +noise -> leakyrelu*sqrt(2)
// B=16, CIN=COUT=512, in 32x32 -> out 64x64, fp32 I/O, fp16 tensor-core GEMM.
// ---------------------------------------------------------------------------

#define NB    16
#define NC    512
#define HIN   32
#define HOUT  64
#define PW    66           // padded spatial (64 + 1 border each side)

static __device__ __half g_xm[(size_t)NB * PW * PW * NC];   // modulated upsampled input, NHWC fp16, zero border
static __device__ __half g_wt[9 * NC * NC];                 // weights per tap: [t][o][i] fp16 (scaled)
static __device__ float  g_wsq[NC * NC];                    // sum_t wk[o,i,t]^2
static __device__ float  g_s[NB * NC];                      // style
static __device__ float  g_demod[NB * NC];                  // demod factors

__device__ __constant__ float kLinScale  = 0.04419417382415922f;   // 1/sqrt(512)
__device__ __constant__ float kConvScale = 0.014731391274719742f;  // 1/sqrt(512*9)

// ---------------- style: s[b,c] = (w[b,:] . lin_w[c,:]) * scale + lin_b[c] --
__global__ void k_style(const float* __restrict__ w,
                        const float* __restrict__ lin_w,
                        const float* __restrict__ lin_b)
{
    int gw   = (blockIdx.x * blockDim.x + threadIdx.x) >> 5;  // warp per (b,c)
    int lane = threadIdx.x & 31;
    if (gw >= NB * NC) return;
    int b = gw >> 9, c = gw & 511;
    const float* wr = w + b * NC;
    const float* lr = lin_w + c * NC;
    float acc = 0.f;
    #pragma unroll 4
    for (int k = lane; k < NC; k += 32) acc += wr[k] * lr[k];
    #pragma unroll
    for (int o = 16; o; o >>= 1) acc += __shfl_xor_sync(0xffffffffu, acc, o);
    if (lane == 0) g_s[gw] = acc * kLinScale + lin_b[c];
}

// -------- weight transform: wt[t][o][i] = conv_w[o][i][t]*scale ; wsq -------
__global__ void k_wt(const float* __restrict__ conv_w)
{
    int idx = blockIdx.x * blockDim.x + threadIdx.x;   // idx = o*512 + i
    if (idx >= NC * NC) return;
    const float* p = conv_w + (size_t)idx * 9;
    float sq = 0.f;
    #pragma unroll
    for (int t = 0; t < 9; t++) {
        float v = p[t] * kConvScale;
        sq += v * v;
        g_wt[t * (NC * NC) + idx] = __float2half_rn(v);
    }
    g_wsq[idx] = sq;
}

// ---- demod[b,o] = rsqrt( sum_i s[b,i]^2 * wsq[o,i] + eps ) -----------------
__global__ void k_demod()
{
    int gw   = (blockIdx.x * blockDim.x + threadIdx.x) >> 5;
    int lane = threadIdx.x & 31;
    if (gw >= NB * NC) return;
    int b = gw >> 9, o = gw & 511;
    const float* sp = g_s + b * NC;
    const float* wp = g_wsq + o * NC;
    float acc = 0.f;
    #pragma unroll 4
    for (int k = lane; k < NC; k += 32) { float sv = sp[k]; acc += sv * sv * wp[k]; }
    #pragma unroll
    for (int oo = 16; oo; oo >>= 1) acc += __shfl_xor_sync(0xffffffffu, acc, oo);
    if (lane == 0) g_demod[gw] = rsqrtf(acc + 1e-8f);
}

// ---- upsample 2x (bilinear, half-pixel, edge-renormalized == clamp) +
//      per-channel style modulation; write NHWC fp16 into padded buffer ------
__global__ void k_upmod(const float* __restrict__ x)
{
    __shared__ float sm[2][64][33];   // [row01][channel][x_in], padded stride 33 (conflict-free)
    __shared__ float ss[64];
    int tid = threadIdx.x;
    int Y = blockIdx.x, cb = blockIdx.y, b = blockIdx.z;
    int c0 = cb * 64;
    int m = Y >> 1;
    int y0, y1; float wy0, wy1;
    if (Y & 1) { y0 = m;                 y1 = min(m + 1, HIN - 1); wy0 = 0.75f; wy1 = 0.25f; }
    else       { y0 = max(m - 1, 0);     y1 = m;                   wy0 = 0.25f; wy1 = 0.75f; }

    for (int lin = tid; lin < 4096; lin += 256) {
        int wv = lin & 31, r = (lin >> 5) & 1, cc = lin >> 6;
        sm[r][cc][wv] = x[(((size_t)b * NC + c0 + cc) * HIN + (r ? y1 : y0)) * HIN + wv];
    }
    if (tid < 64) ss[tid] = g_s[b * NC + c0 + tid];
    __syncthreads();

    for (int lin = tid; lin < 4096; lin += 256) {
        int cc = lin & 63, X = lin >> 6;
        int mm = X >> 1;
        int x0, x1; float wx0, wx1;
        if (X & 1) { x0 = mm;             x1 = min(mm + 1, HIN - 1); wx0 = 0.75f; wx1 = 0.25f; }
        else       { x0 = max(mm - 1, 0); x1 = mm;                   wx0 = 0.25f; wx1 = 0.75f; }
        float v = wy0 * (wx0 * sm[0][cc][x0] + wx1 * sm[0][cc][x1])
                + wy1 * (wx0 * sm[1][cc][x0] + wx1 * sm[1][cc][x1]);
        g_xm[(((size_t)b * PW + (Y + 1)) * PW + (X + 1)) * NC + c0 + cc] =
            __float2half_rn(v * ss[cc]);
    }
}

// ---- zero the 1-pixel border of g_xm ---------------------------------------
__global__ void k_border()
{
    int idx = blockIdx.x * blockDim.x + threadIdx.x;   // 16 * 260 pixels * 64 uint4
    if (idx >= NB * 260 * 64) return;
    int b = idx / (260 * 64);
    int r2 = idx - b * (260 * 64);
    int u = r2 & 63, pix = r2 >> 6;
    int row, col;
    if      (pix < 66)  { row = 0;              col = pix;        }
    else if (pix < 132) { row = 65;             col = pix - 66;   }
    else if (pix < 196) { row = pix - 132 + 1;  col = 0;          }
    else                { row = pix - 196 + 1;  col = 65;         }
    uint4 z = make_uint4(0u, 0u, 0u, 0u);
    *reinterpret_cast<uint4*>(g_xm + (((size_t)b * PW + row) * PW + col) * NC + u * 8) = z;
}

// ---------------------------------------------------------------------------
// conv as 9-tap implicit GEMM: Y[o, pix] = sum_t sum_i Wt[t][o][i] * X[pix+t][i]
// Block tile: M=128 (out ch), N=128 pixels (2 output rows x 64), K-chunk=64 ch.
// B tile (4 padded rows x 66 cols x 64 ch) is reused by all 9 taps.
// SW128 swizzle on both SMEM tiles; ldmatrix per-lane gather handles tap shift.
// ---------------------------------------------------------------------------
#define LDSM4(R0,R1,R2,R3,ADDR)                                              \
    asm volatile("ldmatrix.sync.aligned.m8n8.x4.shared.b16 {%0,%1,%2,%3}, [%4];\n" \
                 : "=r"(R0), "=r"(R1), "=r"(R2), "=r"(R3) : "r"(ADDR))

__global__ __launch_bounds__(256) void k_conv(const float* __restrict__ noise,
                                              const float* __restrict__ nwp,
                                              float* __restrict__ out)
{
    extern __shared__ char smem[];     // [0,16384): A tile 128x64 f16, [16384,50176): B tile 264x64 f16
    const int tid = threadIdx.x;
    const int pb = blockIdx.x, ob = blockIdx.y, b = blockIdx.z;
    const int Ybase = pb * 2;
    const int lane = tid & 31, warp = tid >> 5;
    const int m0 = (warp >> 2) * 64;   // warp M offset (2x4 warp grid)
    const int n0 = (warp & 3) * 32;    // warp N offset
    const uint32_t sA = (uint32_t)__cvta_generic_to_shared(smem);
    const uint32_t sB = sA + 16384;

    float acc[4][4][4];
    #pragma unroll
    for (int i = 0; i < 4; i++)
        #pragma unroll
        for (int j = 0; j < 4; j++)
            #pragma unroll
            for (int k = 0; k < 4; k++) acc[i][j][k] = 0.f;

    const __half* gX = g_xm + (size_t)b * (PW * PW * NC);

    for (int ic = 0; ic < NC; ic += 64) {
        __syncthreads();
        // load B tile: 4 rows x 66 cols x 64 ch  (264 pixels * 8 x 16B units)
        for (int lin = tid; lin < 2112; lin += 256) {
            int u = lin & 7, pix = lin >> 3;
            int pr = pix / 66, px = pix - pr * 66;
            uint4 v = *reinterpret_cast<const uint4*>(
                gX + (((size_t)(Ybase + pr)) * PW + px) * NC + ic + u * 8);
            int lb = pix * 128 + u * 16;
            *reinterpret_cast<uint4*>(smem + 16384 + (lb ^ ((pix & 7) << 4))) = v;
        }
        for (int t = 0; t < 9; t++) {
            __syncthreads();
            // load A tile: 128 x 64 f16 for this tap
            const __half* gA = g_wt + t * (NC * NC) + (ob * 128) * NC + ic;
            {
                int lin = tid;
                #pragma unroll
                for (int j = 0; j < 4; j++) {
                    int u = lin & 7, r = lin >> 3;
                    uint4 v = *reinterpret_cast<const uint4*>(gA + r * NC + u * 8);
                    int lb = r * 128 + u * 16;
                    *reinterpret_cast<uint4*>(smem + (lb ^ ((r & 7) << 4))) = v;
                    lin += 256;
                }
            }
            __syncthreads();
            const int dy = t / 3, dx = t - dy * 3;
            #pragma unroll
            for (int ks = 0; ks < 4; ks++) {
                const int k0 = ks * 16;
                uint32_t a[4][4];
                #pragma unroll
                for (int mt = 0; mt < 4; mt++) {
                    int row = m0 + mt * 16 + (lane & 15);
                    int byteo = row * 128 + (k0 + ((lane >> 4) << 3)) * 2;
                    uint32_t addr = sA + (byteo ^ ((row & 7) << 4));
                    LDSM4(a[mt][0], a[mt][1], a[mt][2], a[mt][3], addr);
                }
                uint32_t bb[4][2];
                #pragma unroll
                for (int nt2 = 0; nt2 < 2; nt2++) {
                    int nl = n0 + nt2 * 16 + ((lane >> 4) << 3) + (lane & 7);
                    int kk = k0 + (((lane >> 3) & 1) << 3);
                    int p = ((nl >> 6) + dy) * PW + (nl & 63) + dx;
                    int byteo = p * 128 + kk * 2;
                    uint32_t addr = sB + (byteo ^ ((p & 7) << 4));
                    uint32_t r0, r1, r2, r3;
                    LDSM4(r0, r1, r2, r3, addr);
                    bb[nt2 * 2][0] = r0; bb[nt2 * 2][1] = r1;
                    bb[nt2 * 2 + 1][0] = r2; bb[nt2 * 2 + 1][1] = r3;
                }
                #pragma unroll
                for (int mt = 0; mt < 4; mt++)
                    #pragma unroll
                    for (int nt = 0; nt < 4; nt++)
                        asm volatile(
                            "mma.sync.aligned.m16n8k16.row.col.f32.f16.f16.f32 "
                            "{%0,%1,%2,%3}, {%4,%5,%6,%7}, {%8,%9}, {%0,%1,%2,%3};\n"
                            : "+f"(acc[mt][nt][0]), "+f"(acc[mt][nt][1]),
                              "+f"(acc[mt][nt][2]), "+f"(acc[mt][nt][3])
                            : "r"(a[mt][0]), "r"(a[mt][1]), "r"(a[mt][2]), "r"(a[mt][3]),
                              "r"(bb[nt][0]), "r"(bb[nt][1]));
            }
        }
    }

    // epilogue: demod, noise, leakyrelu*sqrt2; output NCHW fp32
    const float nw = *nwp;
    #pragma unroll
    for (int mt = 0; mt < 4; mt++) {
        int o = ob * 128 + m0 + mt * 16 + (lane >> 2);
        float d0 = g_demod[b * NC + o];
        float d1 = g_demod[b * NC + o + 8];
        #pragma unroll
        for (int nt = 0; nt < 4; nt++) {
            int n = n0 + nt * 8 + ((lane & 3) << 1);
            int Y = Ybase + (n >> 6), X = n & 63;
            float nz0 = nw * noise[(b * HOUT + Y) * HOUT + X];
            float nz1 = nw * noise[(b * HOUT + Y) * HOUT + X + 1];
            float* p0 = out + ((size_t)(b * NC + o)) * 4096 + Y * 64 + X;
            float* p1 = p0 + 8 * 4096;
            float v;
            v = acc[mt][nt][0] * d0 + nz0; p0[0] = (v >= 0.f ? v : 0.2f * v) * 1.41421356237f;
            v = acc[mt][nt][1] * d0 + nz1; p0[1] = (v >= 0.f ? v : 0.2f * v) * 1.41421356237f;
            v = acc[mt][nt][2] * d1 + nz0; p1[0] = (v >= 0.f ? v : 0.2f * v) * 1.41421356237f;
            v = acc[mt][nt][3] * d1 + nz1; p1[1] = (v >= 0.f ? v : 0.2f * v) * 1.41421356237f;
        }
    }
}

// ---------------------------------------------------------------------------
extern "C" void kernel_launch(void* const* d_in, const int* in_sizes, int n_in,
                              void* d_out, int out_size)
{
    const float* x      = (const float*)d_in[0];
    const float* w      = (const float*)d_in[1];
    const float* noise  = (const float*)d_in[2];
    const float* lin_w  = (const float*)d_in[3];
    const float* lin_b  = (const float*)d_in[4];
    const float* conv_w = (const float*)d_in[5];
    const float* nw     = (const float*)d_in[6];
    float* out = (float*)d_out;

    cudaFuncSetAttribute(k_conv, cudaFuncAttributeMaxDynamicSharedMemorySize, 50176);

    k_style <<<1024, 256>>>(w, lin_w, lin_b);        // 8192 warps: one per (b,c)
    k_wt    <<<1024, 256>>>(conv_w);                 // 262144 threads: one per (o,i)
    k_demod <<<1024, 256>>>();                       // 8192 warps: one per (b,o)
    k_upmod <<<dim3(HOUT, 8, NB), 256>>>(x);         // (Y, c-block of 64, b)
    k_border<<<1040, 256>>>();                       // zero padded border
    k_conv  <<<dim3(32, 4, NB), 256, 50176>>>(noise, nw, out);  // (pixel-blk, o-blk, b)
}